// round 3
// baseline (speedup 1.0000x reference)
#include <cuda_runtime.h>

// SpatialAwareFocalLoss — GB300 sm_103a, round 3.
//  * block-wide prefix sums over {tsum, sigsum} -> window sum = P[hi]-P[lo-1]
//    (replaces the ~21-iter divergent LDS loop with 2 LDS.64).
//    tsum prefix is integer-exact in fp32 -> the (nearby_tgt>0) gate is exact.
//  * single kernel launch: device-scratch partials + ticket counter; last CTA
//    reduces and writes out[0] (counter reset each call -> graph-replay safe).

static constexpr int S    = 1024;  // SEQ_LEN
static constexpr int NC   = 8;     // classes
static constexpr int NLIN = 264;   // line values 0..255 + window slack
static constexpr int MAXB = 256;

__device__ float        g_part[MAXB];
__device__ unsigned int g_cnt = 0;

__global__ __launch_bounds__(1024, 1)
void focal_kernel(const float* __restrict__ pred,
                  const float* __restrict__ target,
                  const int*   __restrict__ token_to_line,
                  float* __restrict__ out,
                  float inv_total, int nblocks)
{
    __shared__ float2 s_pre[S];      // inclusive prefix of {tsum, sigsum}
    __shared__ int    s_line[S];
    __shared__ int    s_first[NLIN]; // lower_bound: first token with line >= v
    __shared__ float2 s_wsum[32];    // per-warp scan totals (then inclusive scan)
    __shared__ float  s_red[32];

    const int b    = blockIdx.x;
    const int i    = threadIdx.x;
    const int lane = i & 31, warp = i >> 5;
    const long base = ((long)b * S + i) * NC;

    const float4 pa = __ldg((const float4*)(pred + base));
    const float4 pb = __ldg((const float4*)(pred + base + 4));
    const float4 ta = __ldg((const float4*)(target + base));
    const float4 tb = __ldg((const float4*)(target + base + 4));
    const int li = token_to_line[b * S + i];

    if (i < NLIN) s_first[i] = S;    // default: past-the-end
    s_line[i] = li;

    float p[NC] = {pa.x, pa.y, pa.z, pa.w, pb.x, pb.y, pb.z, pb.w};
    float t[NC] = {ta.x, ta.y, ta.z, ta.w, tb.x, tb.y, tb.z, tb.w};

    float tsum = 0.0f, sigsum = 0.0f, local = 0.0f;
    #pragma unroll
    for (int c = 0; c < NC; ++c) {
        const float x = p[c];
        const float e = __expf(-fabsf(x));
        const float a = 1.0f / (1.0f + e);        // sigmoid(|x|)
        const float g = e * a;                    // 1 - sigmoid(|x|)
        const float sig  = (x >= 0.0f) ? a : g;
        const float sig1 = (x >= 0.0f) ? g : a;   // 1 - sig
        sigsum += sig;
        tsum   += t[c];
        const float pt  = (t[c] > 0.5f) ? sig : sig1;
        const float omp = (t[c] > 0.5f) ? sig1 : sig;   // 1 - pt
        const float bce = -__logf(pt);
        const float o2  = omp * omp;
        local += 0.01f * o2 * o2 * bce;           // ALPHA*(1-pt)^GAMMA*bce
    }

    // warp-level inclusive scan of (tsum, sigsum)
    float sct = tsum, scs = sigsum;
    #pragma unroll
    for (int o = 1; o < 32; o <<= 1) {
        const float ut = __shfl_up_sync(0xffffffffu, sct, o);
        const float us = __shfl_up_sync(0xffffffffu, scs, o);
        if (lane >= o) { sct += ut; scs += us; }
    }
    if (lane == 31) s_wsum[warp] = make_float2(sct, scs);
    __syncthreads();   // s_line, s_first init, s_wsum ready

    // warp0: inclusive scan of the 32 warp totals
    if (warp == 0) {
        float2 v = s_wsum[lane];
        float a = v.x, s = v.y;
        #pragma unroll
        for (int o = 1; o < 32; o <<= 1) {
            const float ua = __shfl_up_sync(0xffffffffu, a, o);
            const float us = __shfl_up_sync(0xffffffffu, s, o);
            if (lane >= o) { a += ua; s += us; }
        }
        s_wsum[lane] = make_float2(a, s);
    }
    // all threads: fill lower-bound table (each value written by one thread)
    {
        const int prev = (i == 0) ? -1 : s_line[i - 1];
        for (int v = prev + 1; v <= li; ++v) s_first[v] = i;
    }
    __syncthreads();

    const float2 off = (warp > 0) ? s_wsum[warp - 1] : make_float2(0.f, 0.f);
    s_pre[i] = make_float2(sct + off.x, scs + off.y);
    __syncthreads();

    // window [lo, hi] = tokens with |line - li| <= 2 (lines sorted)
    const int vlo = (li >= 2) ? (li - 2) : 0;
    const int lo  = s_first[vlo];
    const int hi  = s_first[li + 3] - 1;
    const int cnt = hi - lo;                  // neighbors excluding self

    const float2 Ph = s_pre[hi];
    const float2 Pl = (lo > 0) ? s_pre[lo - 1] : make_float2(0.f, 0.f);
    const float ntgt = (Ph.x - Pl.x) - tsum;  // exact (integer-valued)
    const float nsig = (Ph.y - Pl.y) - sigsum;

    if (cnt > 0 && ntgt > 0.0f)
        local += 0.03f * nsig / (float)cnt;   // SPATIAL_WEIGHT*0.1*sum_c sig_mean

    // block reduction
    #pragma unroll
    for (int o = 16; o > 0; o >>= 1)
        local += __shfl_xor_sync(0xffffffffu, local, o);
    if (lane == 0) s_red[warp] = local;
    __syncthreads();

    if (warp == 0) {
        float v = s_red[lane];
        #pragma unroll
        for (int o = 16; o > 0; o >>= 1)
            v += __shfl_xor_sync(0xffffffffu, v, o);

        unsigned int ticket = 0;
        if (lane == 0) {
            g_part[b] = v;
            __threadfence();
            ticket = atomicAdd(&g_cnt, 1u) + 1u;
        }
        ticket = __shfl_sync(0xffffffffu, ticket, 0);

        if ((int)ticket == nblocks) {         // last CTA: final reduce
            __threadfence();
            float acc = 0.0f;
            for (int k = lane; k < nblocks; k += 32)
                acc += __ldcg(&g_part[k]);    // L2 read (skip stale L1)
            #pragma unroll
            for (int o = 16; o > 0; o >>= 1)
                acc += __shfl_xor_sync(0xffffffffu, acc, o);
            if (lane == 0) {
                out[0] = acc * inv_total;
                g_cnt = 0;                    // reset for next graph replay
            }
        }
    }
}

extern "C" void kernel_launch(void* const* d_in, const int* in_sizes, int n_in,
                              void* d_out, int out_size)
{
    const float* pred   = (const float*)d_in[0];
    const float* target = (const float*)d_in[1];
    const int*   lines  = (const int*)d_in[2];
    float* out = (float*)d_out;

    const int BS = in_sizes[2];
    const int B  = BS / S;
    const float inv_total = 1.0f / ((float)BS * (float)NC);

    focal_kernel<<<B, 1024>>>(pred, target, lines, out, inv_total, B);
}

// round 4
// speedup vs baseline: 1.2316x; 1.2316x over previous
#include <cuda_runtime.h>

// SpatialAwareFocalLoss — GB300 sm_103a, round 4.
//  * class-split: 2 CTAs per sequence (classes 0-3 / 4-7) -> 128 CTAs,
//    halves the heavy per-class math per CTA, no halo needed (penalty is
//    additive over classes; gate uses full target sums = 8 cheap FADDs).
//  * line-binning: shared atomicAdd into 256 line bins (packed int cnt+tsum,
//    float sigsum), window = 5 bin reads. No scan, no lower-bound table.

static constexpr int S    = 1024;   // SEQ_LEN
static constexpr int NBIN = 260;    // line 0..255, +2 offset both sides
static constexpr int MAXB = 512;

__device__ float        g_part[MAXB];
__device__ unsigned int g_cnt = 0;

__global__ __launch_bounds__(1024, 1)
void focal_kernel(const float* __restrict__ pred,
                  const float* __restrict__ target,
                  const int*   __restrict__ token_to_line,
                  float* __restrict__ out,
                  float inv_total, int nblocks)
{
    __shared__ int   s_bin_i[NBIN];  // cnt + (tsum<<16), index = line + 2
    __shared__ float s_bin_f[NBIN];  // partial (this half's classes) sigmoid sum
    __shared__ float s_red[32];

    const int bid  = blockIdx.x;
    const int b    = bid >> 1;        // sequence
    const int half = bid & 1;         // class half: 0 -> c0..3, 1 -> c4..7
    const int i    = threadIdx.x;
    const int lane = i & 31, warp = i >> 5;

    if (i < NBIN) { s_bin_i[i] = 0; s_bin_f[i] = 0.0f; }

    const long tok  = (long)b * S + i;
    const long base = tok * 8;

    const float4 p4 = __ldg((const float4*)(pred + base + half * 4));
    const float4 ta = __ldg((const float4*)(target + base));
    const float4 tb = __ldg((const float4*)(target + base + 4));
    const int    li = __ldg(token_to_line + tok);

    __syncthreads();   // bins zeroed before any atomic lands

    // full-target token sum (exact small integer) -> window gate
    const int tint = (int)(ta.x + ta.y + ta.z + ta.w + tb.x + tb.y + tb.z + tb.w);

    const float4 ts = half ? tb : ta;
    float p[4] = {p4.x, p4.y, p4.z, p4.w};
    float t[4] = {ts.x, ts.y, ts.z, ts.w};

    float sigsum = 0.0f, local = 0.0f;
    #pragma unroll
    for (int c = 0; c < 4; ++c) {
        const float x = p[c];
        const float e = __expf(-fabsf(x));
        const float a = 1.0f / (1.0f + e);        // sigmoid(|x|)
        const float g = e * a;                    // 1 - sigmoid(|x|)
        const float sig  = (x >= 0.0f) ? a : g;
        const float sig1 = (x >= 0.0f) ? g : a;   // 1 - sig
        sigsum += sig;
        const float pt  = (t[c] > 0.5f) ? sig : sig1;
        const float omp = (t[c] > 0.5f) ? sig1 : sig;   // 1 - pt
        const float bce = -__logf(pt);
        const float o2  = omp * omp;
        local += 0.01f * o2 * o2 * bce;           // ALPHA*(1-pt)^GAMMA*bce
    }

    const int self_i = 1 + (tint << 16);
    atomicAdd(&s_bin_i[li + 2], self_i);
    atomicAdd(&s_bin_f[li + 2], sigsum);
    __syncthreads();

    // window lines [li-2, li+2] -> bins [li, li+4]; exclude self
    int   ci   = -self_i;
    float nsig = -sigsum;
    #pragma unroll
    for (int k = 0; k < 5; ++k) {
        ci   += s_bin_i[li + k];
        nsig += s_bin_f[li + k];
    }
    const int cnt  = ci & 0xffff;     // neighbors excluding self
    const int ntgt = ci >> 16;        // exact integer nearby target sum

    if (cnt > 0 && ntgt > 0)
        local += 0.03f * nsig / (float)cnt;   // SPATIAL_WEIGHT*0.1*Σ_c sig_mean

    // block reduction -> one partial per CTA
    #pragma unroll
    for (int o = 16; o > 0; o >>= 1)
        local += __shfl_xor_sync(0xffffffffu, local, o);
    if (lane == 0) s_red[warp] = local;
    __syncthreads();

    if (warp == 0) {
        float v = s_red[lane];
        #pragma unroll
        for (int o = 16; o > 0; o >>= 1)
            v += __shfl_xor_sync(0xffffffffu, v, o);

        unsigned int ticket = 0;
        if (lane == 0) {
            g_part[bid] = v;
            __threadfence();
            ticket = atomicAdd(&g_cnt, 1u) + 1u;
        }
        ticket = __shfl_sync(0xffffffffu, ticket, 0);

        if ((int)ticket == nblocks) {           // last CTA: final reduce
            __threadfence();
            float acc = 0.0f;
            for (int k = lane; k < nblocks; k += 32)
                acc += __ldcg(&g_part[k]);
            #pragma unroll
            for (int o = 16; o > 0; o >>= 1)
                acc += __shfl_xor_sync(0xffffffffu, acc, o);
            if (lane == 0) {
                out[0] = acc * inv_total;
                g_cnt = 0;                      // reset for next graph replay
            }
        }
    }
}

extern "C" void kernel_launch(void* const* d_in, const int* in_sizes, int n_in,
                              void* d_out, int out_size)
{
    const float* pred   = (const float*)d_in[0];
    const float* target = (const float*)d_in[1];
    const int*   lines  = (const int*)d_in[2];
    float* out = (float*)d_out;

    const int BS = in_sizes[2];
    const int B  = BS / S;
    const int nblocks = 2 * B;                 // 2 class-halves per sequence
    const float inv_total = 1.0f / ((float)BS * 8.0f);

    focal_kernel<<<nblocks, 1024>>>(pred, target, lines, out, inv_total, nblocks);
}